// round 7
// baseline (speedup 1.0000x reference)
#include <cuda_runtime.h>
#include <math.h>

// RoIPool (max) — features (2,256,50,76) f32, rois (128,5) f32 -> out (128,256,7,7) f32
// Bin arithmetic matches the XLA-lowered JAX reference bit-for-bit (x/7 lowered to
// x * fp32(1/7)).
// R7 structure (channel-persistent SMEM):
//   block = (channel, roi-quarter). Stage BOTH batch planes of this channel into
//   SMEM via coalesced float4 loads (rows are 16B-aligned, 76 = 19 float4s), then
//   compute 32 rois x 49 bins entirely from shared memory. Bin-bound tables are
//   computed once per block. Any bin size is handled (window subset of plane).

#define C_      256
#define H_      50
#define W_      76
#define PLANE_  (H_ * W_)        // 3800
#define SROW_   77               // padded smem row stride (odd -> bank spread)
#define SPLANE_ (H_ * SROW_)     // 3850
#define PH_     7
#define PW_     7
#define NROIS_  128
#define RPB_    32               // rois per block
#define TPB_    256
#define SCALE_  0.0625f
// fp32 nearest to 1/7 (0x3E124925)
#define RECIP7_ 0.14285714924335479736328125f

__global__ __launch_bounds__(TPB_)
void roipool_kernel(const float* __restrict__ feat,
                    const float* __restrict__ rois,
                    float* __restrict__ out)
{
    const int c       = blockIdx.x;            // channel 0..255
    const int roiBase = blockIdx.y * RPB_;     // 0,32,64,96
    const int tid     = threadIdx.x;

    __shared__ float splane[2 * SPLANE_];      // both batch planes, padded rows
    __shared__ int2  s_h[RPB_][PH_];           // {hstart, hend}
    __shared__ int2  s_w[RPB_][PW_];           // {wstart, wend}
    __shared__ int   s_b[RPB_];                // batch index

    // ---- Phase A1: per-roi bin tables (bit-exact XLA arithmetic) ----
    for (int idx = tid; idx < RPB_ * 14; idx += TPB_) {
        const int rl = idx / 14;
        const int k  = idx - rl * 14;
        const float* r = rois + (roiBase + rl) * 5;
        if (k < PH_) {
            const int y1 = (int)rintf(__fmul_rn(r[2], SCALE_));
            const int y2 = (int)rintf(__fmul_rn(r[4], SCALE_));
            const float bh = __fmul_rn((float)max(y2 - y1 + 1, 1), RECIP7_);
            int hs = (int)floorf(__fmul_rn((float)k,       bh)) + y1;
            int he = (int)ceilf (__fmul_rn((float)(k + 1), bh)) + y1;
            hs = min(max(hs, 0), H_);
            he = min(max(he, 0), H_);
            s_h[rl][k] = make_int2(hs, he);
            if (k == 0) s_b[rl] = (int)r[0];
        } else {
            const int p  = k - PH_;
            const int x1 = (int)rintf(__fmul_rn(r[1], SCALE_));
            const int x2 = (int)rintf(__fmul_rn(r[3], SCALE_));
            const float bw = __fmul_rn((float)max(x2 - x1 + 1, 1), RECIP7_);
            int ws = (int)floorf(__fmul_rn((float)p,       bw)) + x1;
            int we = (int)ceilf (__fmul_rn((float)(p + 1), bw)) + x1;
            ws = min(max(ws, 0), W_);
            we = min(max(we, 0), W_);
            s_w[rl][p] = make_int2(ws, we);
        }
    }

    // ---- Phase A2: stage both batch planes of channel c (coalesced float4) ----
    #pragma unroll
    for (int bb = 0; bb < 2; ++bb) {
        const float4* g = (const float4*)(feat + ((size_t)bb * C_ + c) * PLANE_);
        float* d = splane + bb * SPLANE_;
        for (int i4 = tid; i4 < PLANE_ / 4; i4 += TPB_) {   // 950 float4s
            const float4 v = __ldg(g + i4);
            const int row = i4 / 19;             // 19 float4s per row
            const int c4  = (i4 - row * 19) * 4;
            float* p = d + row * SROW_ + c4;
            p[0] = v.x; p[1] = v.y; p[2] = v.z; p[3] = v.w;
        }
    }
    __syncthreads();

    // ---- Phase B: pool 32 rois x 49 bins from SMEM ----
    const int NOUT = RPB_ * PH_ * PW_;          // 1568
    for (int o = tid; o < NOUT; o += TPB_) {
        const int rl = o / (PH_ * PW_);
        const int s  = o - rl * (PH_ * PW_);
        const int ph = s / PW_;
        const int pw = s - ph * PW_;

        const int2 hb = s_h[rl][ph];
        const int2 wb = s_w[rl][pw];

        const float* sp = splane + s_b[rl] * SPLANE_;

        float m = -3.402823466e+38f;            // -FLT_MAX
        for (int i = hb.x; i < hb.y; ++i) {
            const float* row = sp + i * SROW_;
            #pragma unroll 4
            for (int j = wb.x; j < wb.y; ++j)
                m = fmaxf(m, row[j]);
        }
        if (hb.y <= hb.x || wb.y <= wb.x) m = 0.0f;   // empty bin -> 0

        out[(size_t)(roiBase + rl) * (C_ * PH_ * PW_) + c * (PH_ * PW_) + s] = m;
    }
}

extern "C" void kernel_launch(void* const* d_in, const int* in_sizes, int n_in,
                              void* d_out, int out_size)
{
    // Autodetect input order by element count (rois = 640 elems, features = 1,945,600).
    const float* feat;
    const float* rois;
    if (in_sizes[0] == NROIS_ * 5) {
        rois = (const float*)d_in[0];
        feat = (const float*)d_in[1];
    } else {
        feat = (const float*)d_in[0];
        rois = (const float*)d_in[1];
    }
    float* out = (float*)d_out;

    dim3 block(TPB_);
    dim3 grid(C_, NROIS_ / RPB_);    // 256 channels x 4 roi-quarters = 1024 blocks
    roipool_kernel<<<grid, block>>>(feat, rois, out);
}